// round 15
// baseline (speedup 1.0000x reference)
#include <cuda_runtime.h>
#include <cuda_fp16.h>
#include <math.h>

#define VSZ 5000
#define HSZ 1024
#define ESZ 512
#define BSZ 64
#define TSZ 256
#define H4  (4 * HSZ)
#define MROWS (BSZ * TSZ)   // 16384
#define NTILE 79            // ceil(5000/64)
#define NITEMS (TSZ * NTILE)

// ---------------- scratch ---------------------------------------------------
#define FRAGBUF (4 * 64 * 32 * 4)                     // uint32 per step-buffer
__device__ unsigned g_xf[(size_t)TSZ * FRAGBUF / 2];  // x fp16 A-frags (K=512)
__device__ unsigned g_h1f[(size_t)TSZ * FRAGBUF];     // h1 frags, all steps (32MB)
__device__ unsigned g_h2f[(size_t)TSZ * FRAGBUF];     // h2 frags, all steps (32MB)
__device__ unsigned g_wf1[64 * 8 * 32 * 64];          // W_ih1 fp16 B-frags (4MB)
__device__ unsigned g_wf2[64 * 8 * 64 * 64];          // W_ih2 fp16 B-frags (8MB)
__device__ unsigned g_lwf[(size_t)NTILE * 8 * 64 * 64];// lin_W fp16 B-frags (10.4MB)
__device__ unsigned g_ctr[2 * TSZ];
__device__ unsigned g_q;                              // projection work queue

// ---------------- helpers ---------------------------------------------------
__device__ __forceinline__ unsigned pack2(float x, float y) {
    __half2 h = __floats2half2_rn(x, y);
    return *(unsigned*)&h;
}
__device__ __forceinline__ void mma16(float* c, const unsigned* a, const unsigned* b) {
    asm volatile(
        "mma.sync.aligned.m16n8k16.row.col.f32.f16.f16.f32 "
        "{%0,%1,%2,%3}, {%4,%5,%6,%7}, {%8,%9}, {%0,%1,%2,%3};\n"
        : "+f"(c[0]), "+f"(c[1]), "+f"(c[2]), "+f"(c[3])
        : "r"(a[0]), "r"(a[1]), "r"(a[2]), "r"(a[3]), "r"(b[0]), "r"(b[1]));
}
__device__ __forceinline__ void red_release(unsigned* p) {
    asm volatile("red.release.gpu.global.add.u32 [%0], 1;" :: "l"(p) : "memory");
}
__device__ __forceinline__ unsigned ld_acquire(const unsigned* p) {
    unsigned v;
    asm volatile("ld.acquire.gpu.global.b32 %0, [%1];" : "=r"(v) : "l"(p) : "memory");
    return v;
}
__device__ __forceinline__ float tanha(float x) {
    float y; asm("tanh.approx.f32 %0, %1;" : "=f"(y) : "f"(x)); return y;
}
__device__ __forceinline__ float sigm(float x) {
    return fmaf(0.5f, tanha(0.5f * x), 0.5f);
}
#define BARG1() asm volatile("bar.sync 1, 256;" ::: "memory")
#define BARG2() asm volatile("bar.sync 2, 256;" ::: "memory")

// ---------------- small kernels ----------------------------------------------
__global__ void zero_ctr_kernel() {
    g_ctr[threadIdx.x] = 0u;
    if (threadIdx.x == 0) g_q = 0u;
}

__global__ void embed_frag(const int* __restrict__ input,
                           const float* __restrict__ embedW)
{
    int row = blockIdx.x;            // b*TSZ + t
    int b = row >> 8, t = row & 255;
    int idx = input[row];
    int k = threadIdx.x * 4;
    float4 v = *(const float4*)(embedW + (size_t)idx * ESZ + k);
    int mt = b >> 4, ml = b & 15;
    int c = k >> 4, kk = k & 15;
    int e  = ((ml >= 8) ? 1 : 0) + ((kk >= 8) ? 2 : 0);
    int lp = (ml & 7) * 4 + ((kk & 7) >> 1);
    unsigned* base = g_xf + ((size_t)((t * 4 + mt) * 32 + c) * 32) * 4;
    base[lp * 4 + e]       = pack2(v.x, v.y);
    base[(lp + 1) * 4 + e] = pack2(v.z, v.w);
}

__global__ void pack_wf1(const float* __restrict__ Wih1)
{
    int bn = blockIdx.x, h0 = bn * 16;
    for (int idx = threadIdx.x; idx < 64 * 256; idx += 256) {
        int nl = idx >> 8, k = (idx & 255) * 2;
        int g = nl >> 4, u = nl & 15;
        float2 v = *(const float2*)&Wih1[(size_t)(g * HSZ + h0 + u) * ESZ + k];
        int c = k >> 4, kk = k & 15;
        int tn = nl >> 3, rr = nl & 7, qq = (kk & 7) >> 1, f = (kk >= 8) ? 1 : 0;
        g_wf1[((size_t)(bn * 8 + tn) * 32 + c) * 64 + (rr * 4 + qq) * 2 + f] = pack2(v.x, v.y);
    }
}

__global__ void pack_wf2(const float* __restrict__ Wih2)
{
    int bn = blockIdx.x, h0 = bn * 16;
    for (int idx = threadIdx.x; idx < 64 * 512; idx += 256) {
        int nl = idx >> 9, k = (idx & 511) * 2;
        int g = nl >> 4, u = nl & 15;
        float2 v = *(const float2*)&Wih2[(size_t)(g * HSZ + h0 + u) * HSZ + k];
        int c = k >> 4, kk = k & 15;
        int tn = nl >> 3, rr = nl & 7, qq = (kk & 7) >> 1, f = (kk >= 8) ? 1 : 0;
        g_wf2[((size_t)(bn * 8 + tn) * 64 + c) * 64 + (rr * 4 + qq) * 2 + f] = pack2(v.x, v.y);
    }
}

// lin_W (5000 x 1024) -> fp16 B-frags, rows padded with zeros to 79*64
__global__ void pack_lwf(const float* __restrict__ linW)
{
    int nb = blockIdx.x, n0 = nb * 64;
    for (int idx = threadIdx.x; idx < 64 * 512; idx += 256) {
        int nl = idx >> 9, k = (idx & 511) * 2;
        int n = n0 + nl;
        float2 v = make_float2(0.f, 0.f);
        if (n < VSZ) v = *(const float2*)&linW[(size_t)n * HSZ + k];
        int c = k >> 4, kk = k & 15;
        int tn = nl >> 3, rr = nl & 7, qq = (kk & 7) >> 1, f = (kk >= 8) ? 1 : 0;
        g_lwf[((size_t)(nb * 8 + tn) * 64 + c) * 64 + (rr * 4 + qq) * 2 + f] = pack2(v.x, v.y);
    }
}

// ---------------- unified persistent kernel ---------------------------------
// 148 blocks x 512 threads:
//   blocks 0..63   : layer-1 recurrence (then join projection queue)
//   blocks 64..127 : layer-2 recurrence (then join projection queue)
//   blocks 128..147: projection workers from t=0 (queue gated on l2c[t])
__global__ void __launch_bounds__(512, 1)
lstm_dual(const float* __restrict__ Whh1,
          const float* __restrict__ bi1,  const float* __restrict__ bh1,
          const float* __restrict__ Whh2,
          const float* __restrict__ bi2,  const float* __restrict__ bh2,
          const float* __restrict__ lin_b, float* __restrict__ out)
{
    extern __shared__ unsigned smu[];
    float* Gb = (float*)(smu + 32768);    // [4 grp][64][68]
    const int tid = threadIdx.x, lane = tid & 31, wid = tid >> 5;
    const int r = lane >> 2, q = lane & 3;
    unsigned* l1c = g_ctr;
    unsigned* l2c = g_ctr + TSZ;
    const bool isWorker = (blockIdx.x >= 128);

    if (!isWorker) {
        const int mt = wid & 3;
        const int kh = (wid >> 2) & 1;
        const int role = wid >> 3;
        const int grp = role * 2 + kh;
        const bool isL2 = (blockIdx.x >= 64);
        const int bn = isL2 ? (blockIdx.x - 64) : blockIdx.x;
        const int h0 = bn * 16;

        // ---- load W_hh slice into SMEM fp16 B-frags (once) ----
        {
            const float* Whh = isL2 ? Whh2 : Whh1;
            for (int idx = tid; idx < 64 * 512; idx += 512) {
                int nl = idx >> 9, k = (idx & 511) * 2;
                int g = nl >> 4, u = nl & 15;
                float2 v = *(const float2*)&Whh[(size_t)(g * HSZ + h0 + u) * HSZ + k];
                int c = k >> 4, kk = k & 15;
                int tn = nl >> 3, rr = nl & 7, qq = (kk & 7) >> 1, f = (kk >= 8) ? 1 : 0;
                smu[((tn * 64 + c) * 32 + rr * 4 + qq) * 2 + f] = pack2(v.x, v.y);
            }
        }
        __syncthreads();

        // epilogue mapping: thread -> col jb, rows rg*2, rg*2+1
        const int jb = tid & 15, rg = tid >> 4;
        float bia[4];
        {
            const float* bA = isL2 ? bi2 : bi1;
            const float* bB = isL2 ? bh2 : bh1;
            #pragma unroll
            for (int g = 0; g < 4; g++)
                bia[g] = bA[g * HSZ + h0 + jb] + bB[g * HSZ + h0 + jb];
        }
        int pk[2];
        #pragma unroll
        for (int i = 0; i < 2; i++) {
            int ri = rg * 2 + i, mti = ri >> 4, ml = ri & 15;
            int lp = (ml & 7) * 4 + ((jb & 7) >> 1);
            int e  = ((ml >= 8) ? 1 : 0) + ((jb >= 8) ? 2 : 0);
            pk[i]  = (((mti * 64 + bn) * 32 + lp) * 4 + e) * 2 + (jb & 1);
        }
        float cst[2] = {0.f, 0.f};

        for (int t = 0; t < TSZ; t++) {
            float acc[8][4];
            #pragma unroll
            for (int i = 0; i < 8; i++)
                #pragma unroll
                for (int j = 0; j < 4; j++) acc[i][j] = 0.f;

            if (!isL2) {
                if (role == 0) {
                    // x-part: K=512, W from L2, no dependency
                    const uint4* ax = (const uint4*)g_xf
                                      + ((size_t)(t * 4 + mt) * 32 + kh * 16) * 32 + lane;
                    const unsigned* wg = g_wf1 + ((size_t)(bn * 8) * 32 + kh * 16) * 64 + lane * 2;
                    #pragma unroll 8
                    for (int c = 0; c < 16; c++) {
                        uint4 a4 = __ldcg(ax + c * 32);
                        unsigned af[4] = { a4.x, a4.y, a4.z, a4.w };
                        #pragma unroll
                        for (int tn = 0; tn < 8; tn++) {
                            const uint2 b2 = __ldg((const uint2*)(wg + ((size_t)tn * 32 + c) * 64));
                            unsigned bg[2] = { b2.x, b2.y };
                            mma16(acc[tn], af, bg);
                        }
                    }
                } else if (t > 0) {
                    if (tid == 256) { while (ld_acquire(&l1c[t - 1]) < 64) { } }
                    BARG2();
                    const uint4* ah = (const uint4*)g_h1f + (size_t)(t - 1) * (FRAGBUF / 4)
                                      + (mt * 64 + kh * 32) * 32 + lane;
                    #pragma unroll 8
                    for (int c = 0; c < 32; c++) {
                        uint4 a4 = __ldcg(ah + c * 32);
                        unsigned af[4] = { a4.x, a4.y, a4.z, a4.w };
                        #pragma unroll
                        for (int tn = 0; tn < 8; tn++) {
                            const unsigned* p = smu + (tn * 64 + kh * 32 + c) * 64 + lane * 2;
                            unsigned bg[2] = { p[0], p[1] };
                            mma16(acc[tn], af, bg);
                        }
                    }
                }
            } else {
                if (role == 0) {
                    if (t > 0) {
                        if (tid == 0) { while (ld_acquire(&l2c[t - 1]) < 64) { } }
                        BARG1();
                        const uint4* ah = (const uint4*)g_h2f + (size_t)(t - 1) * (FRAGBUF / 4)
                                          + (mt * 64 + kh * 32) * 32 + lane;
                        #pragma unroll 8
                        for (int c = 0; c < 32; c++) {
                            uint4 a4 = __ldcg(ah + c * 32);
                            unsigned af[4] = { a4.x, a4.y, a4.z, a4.w };
                            #pragma unroll
                            for (int tn = 0; tn < 8; tn++) {
                                const unsigned* p = smu + (tn * 64 + kh * 32 + c) * 64 + lane * 2;
                                unsigned bg[2] = { p[0], p[1] };
                                mma16(acc[tn], af, bg);
                            }
                        }
                    }
                } else {
                    if (tid == 256) { while (ld_acquire(&l1c[t]) < 64) { } }
                    BARG2();
                    const uint4* ah1 = (const uint4*)g_h1f + (size_t)t * (FRAGBUF / 4)
                                       + (mt * 64 + kh * 32) * 32 + lane;
                    const unsigned* wg = g_wf2 + ((size_t)(bn * 8) * 64 + kh * 32) * 64 + lane * 2;
                    #pragma unroll 8
                    for (int c = 0; c < 32; c++) {
                        uint4 a4 = __ldcg(ah1 + c * 32);
                        unsigned af[4] = { a4.x, a4.y, a4.z, a4.w };
                        #pragma unroll
                        for (int tn = 0; tn < 8; tn++) {
                            const uint2 b2 = __ldg((const uint2*)(wg + ((size_t)tn * 64 + c) * 64));
                            unsigned bg[2] = { b2.x, b2.y };
                            mma16(acc[tn], af, bg);
                        }
                    }
                }
            }

            // ---- stage partial sums (per group) ----
            {
                float* gb = &Gb[grp * 64 * 68];
                #pragma unroll
                for (int tn = 0; tn < 8; tn++) {
                    int col = tn * 8 + 2 * q;
                    gb[(mt * 16 + r    ) * 68 + col]     = acc[tn][0];
                    gb[(mt * 16 + r    ) * 68 + col + 1] = acc[tn][1];
                    gb[(mt * 16 + r + 8) * 68 + col]     = acc[tn][2];
                    gb[(mt * 16 + r + 8) * 68 + col + 1] = acc[tn][3];
                }
            }
            __syncthreads();

            // ---- cell update: 2 rows per thread; MUFU.TANH activations ----
            __half* hfo = (__half*)((isL2 ? g_h2f : g_h1f) + (size_t)t * FRAGBUF);
            #pragma unroll
            for (int i = 0; i < 2; i++) {
                int ri = rg * 2 + i;
                float iv = bia[0], fv = bia[1], gv = bia[2], ov = bia[3];
                #pragma unroll
                for (int g = 0; g < 4; g++) {
                    const float* gb = &Gb[g * 64 * 68 + ri * 68];
                    iv += gb[jb]; fv += gb[16 + jb]; gv += gb[32 + jb]; ov += gb[48 + jb];
                }
                float si = sigm(iv), sf = sigm(fv), so = sigm(ov);
                float cn = sf * cst[i] + si * tanha(gv);
                float hn = so * tanha(cn);
                cst[i] = cn;
                hfo[pk[i]] = __float2half_rn(hn);
            }
            __syncthreads();           // h-frag STGs ordered before release (cumulativity)
            if (tid == 0) red_release(isL2 ? &l2c[t] : &l1c[t]);
        }
        __syncthreads();               // recurrence done; smu[0] now reusable
    }

    // ---------------- projection work queue -------------------------------
    // item = t * NTILE + nb; gated on l2c[t]. 16 warps = 4 m-tiles x 4 n-quarters.
    {
        const int mt2 = wid & 3, nq = wid >> 2;
        for (;;) {
            if (tid == 0) smu[0] = atomicAdd(&g_q, 1u);
            __syncthreads();
            unsigned idx = smu[0];
            if (idx >= NITEMS) break;
            int t = idx / NTILE, nb2 = idx - t * NTILE;
            if (tid == 0) { while (ld_acquire(&l2c[t]) < 64) { } }
            __syncthreads();           // acquire + protects smu[0] reuse

            float pa[2][4];
            #pragma unroll
            for (int i = 0; i < 2; i++)
                #pragma unroll
                for (int j = 0; j < 4; j++) pa[i][j] = 0.f;

            const uint4* ab = (const uint4*)g_h2f + (size_t)t * (FRAGBUF / 4)
                              + (mt2 * 64) * 32 + lane;
            const unsigned* wg = g_lwf + ((size_t)(nb2 * 8 + nq * 2) * 64) * 64 + lane * 2;

            #pragma unroll 8
            for (int c = 0; c < 64; c++) {
                uint4 a4 = __ldcg(ab + c * 32);                 // same-kernel data: bypass L1
                unsigned af[4] = { a4.x, a4.y, a4.z, a4.w };
                #pragma unroll
                for (int tn = 0; tn < 2; tn++) {
                    const uint2 b2 = __ldg((const uint2*)(wg + ((size_t)tn * 64 + c) * 64));
                    unsigned bg[2] = { b2.x, b2.y };
                    mma16(pa[tn], af, bg);
                }
            }

            #pragma unroll
            for (int tn = 0; tn < 2; tn++) {
                int n = nb2 * 64 + (nq * 2 + tn) * 8 + 2 * q;
                int b0r = mt2 * 16 + r;
                if (n + 1 < VSZ) {
                    float bb0 = lin_b[n], bb1 = lin_b[n + 1];
                    float2 v0 = make_float2(pa[tn][0] + bb0, pa[tn][1] + bb1);
                    float2 v1 = make_float2(pa[tn][2] + bb0, pa[tn][3] + bb1);
                    *(float2*)&out[((size_t)b0r * TSZ + t) * VSZ + n]       = v0;
                    *(float2*)&out[((size_t)(b0r + 8) * TSZ + t) * VSZ + n] = v1;
                } else if (n < VSZ) {
                    float bb0 = lin_b[n];
                    out[((size_t)b0r * TSZ + t) * VSZ + n]       = pa[tn][0] + bb0;
                    out[((size_t)(b0r + 8) * TSZ + t) * VSZ + n] = pa[tn][2] + bb0;
                }
            }
        }
    }
}

// ---------------- launch ----------------------------------------------------
#define SMEM_DUAL (32768 * 4 + 4 * 64 * 68 * 4)   // 200704 bytes

extern "C" void kernel_launch(void* const* d_in, const int* in_sizes, int n_in,
                              void* d_out, int out_size)
{
    const int*   input  = (const int*)  d_in[0];
    const float* embedW = (const float*)d_in[2];
    const float* W_ih1  = (const float*)d_in[3];
    const float* W_hh1  = (const float*)d_in[4];
    const float* b_ih1  = (const float*)d_in[5];
    const float* b_hh1  = (const float*)d_in[6];
    const float* W_ih2  = (const float*)d_in[7];
    const float* W_hh2  = (const float*)d_in[8];
    const float* b_ih2  = (const float*)d_in[9];
    const float* b_hh2  = (const float*)d_in[10];
    const float* lin_W  = (const float*)d_in[11];
    const float* lin_b  = (const float*)d_in[12];
    float* out = (float*)d_out;

    cudaFuncSetAttribute(lstm_dual,
                         cudaFuncAttributeMaxDynamicSharedMemorySize, SMEM_DUAL);

    zero_ctr_kernel<<<1, 2 * TSZ>>>();
    embed_frag<<<MROWS, 128>>>(input, embedW);
    pack_wf1<<<64, 256>>>(W_ih1);
    pack_wf2<<<64, 256>>>(W_ih2);
    pack_lwf<<<NTILE, 256>>>(lin_W);

    lstm_dual<<<148, 512, SMEM_DUAL>>>(W_hh1, b_ih1, b_hh1,
                                       W_hh2, b_ih2, b_hh2,
                                       lin_b, out);
}

// round 16
// speedup vs baseline: 1.1530x; 1.1530x over previous
#include <cuda_runtime.h>
#include <cuda_fp16.h>
#include <math.h>

#define VSZ 5000
#define HSZ 1024
#define ESZ 512
#define BSZ 64
#define TSZ 256
#define H4  (4 * HSZ)
#define MROWS (BSZ * TSZ)   // 16384
#define NTILE 79            // ceil(5000/64)
#define NITEMS2 ((TSZ / 2) * NTILE)   // 2-timestep work items

// ---------------- scratch ---------------------------------------------------
#define FRAGBUF (4 * 64 * 32 * 4)                     // uint32 per step-buffer
__device__ unsigned g_xf[(size_t)TSZ * FRAGBUF / 2];  // x fp16 A-frags (K=512)
__device__ unsigned g_h1f[(size_t)TSZ * FRAGBUF];     // h1 frags, all steps (32MB)
__device__ unsigned g_h2f[(size_t)TSZ * FRAGBUF];     // h2 frags, all steps (32MB)
__device__ unsigned g_wf1[64 * 8 * 32 * 64];          // W_ih1 fp16 B-frags (4MB)
__device__ unsigned g_wf2[64 * 8 * 64 * 64];          // W_ih2 fp16 B-frags (8MB)
__device__ unsigned g_lwf[(size_t)NTILE * 8 * 64 * 64];// lin_W fp16 B-frags (10.4MB)
__device__ unsigned g_ctr[2 * TSZ];
__device__ unsigned g_q;                              // projection work queue

// ---------------- helpers ---------------------------------------------------
__device__ __forceinline__ unsigned pack2(float x, float y) {
    __half2 h = __floats2half2_rn(x, y);
    return *(unsigned*)&h;
}
__device__ __forceinline__ void mma16(float* c, const unsigned* a, const unsigned* b) {
    asm volatile(
        "mma.sync.aligned.m16n8k16.row.col.f32.f16.f16.f32 "
        "{%0,%1,%2,%3}, {%4,%5,%6,%7}, {%8,%9}, {%0,%1,%2,%3};\n"
        : "+f"(c[0]), "+f"(c[1]), "+f"(c[2]), "+f"(c[3])
        : "r"(a[0]), "r"(a[1]), "r"(a[2]), "r"(a[3]), "r"(b[0]), "r"(b[1]));
}
__device__ __forceinline__ void red_release(unsigned* p) {
    asm volatile("red.release.gpu.global.add.u32 [%0], 1;" :: "l"(p) : "memory");
}
__device__ __forceinline__ unsigned ld_acquire(const unsigned* p) {
    unsigned v;
    asm volatile("ld.acquire.gpu.global.b32 %0, [%1];" : "=r"(v) : "l"(p) : "memory");
    return v;
}
__device__ __forceinline__ float tanha(float x) {
    float y; asm("tanh.approx.f32 %0, %1;" : "=f"(y) : "f"(x)); return y;
}
__device__ __forceinline__ float sigm(float x) {
    return fmaf(0.5f, tanha(0.5f * x), 0.5f);
}
#define BARG1() asm volatile("bar.sync 1, 256;" ::: "memory")
#define BARG2() asm volatile("bar.sync 2, 256;" ::: "memory")

// ---------------- small kernels ----------------------------------------------
__global__ void zero_ctr_kernel() {
    g_ctr[threadIdx.x] = 0u;
    if (threadIdx.x == 0) g_q = 0u;
}

__global__ void embed_frag(const int* __restrict__ input,
                           const float* __restrict__ embedW)
{
    int row = blockIdx.x;            // b*TSZ + t
    int b = row >> 8, t = row & 255;
    int idx = input[row];
    int k = threadIdx.x * 4;
    float4 v = *(const float4*)(embedW + (size_t)idx * ESZ + k);
    int mt = b >> 4, ml = b & 15;
    int c = k >> 4, kk = k & 15;
    int e  = ((ml >= 8) ? 1 : 0) + ((kk >= 8) ? 2 : 0);
    int lp = (ml & 7) * 4 + ((kk & 7) >> 1);
    unsigned* base = g_xf + ((size_t)((t * 4 + mt) * 32 + c) * 32) * 4;
    base[lp * 4 + e]       = pack2(v.x, v.y);
    base[(lp + 1) * 4 + e] = pack2(v.z, v.w);
}

// grid (64, 4): blockIdx.y splits the 16384 items
__global__ void pack_wf1(const float* __restrict__ Wih1)
{
    int bn = blockIdx.x, h0 = bn * 16;
    int base = blockIdx.y * 4096;
    for (int idx = base + threadIdx.x; idx < base + 4096; idx += 256) {
        int nl = idx >> 8, k = (idx & 255) * 2;
        int g = nl >> 4, u = nl & 15;
        float2 v = *(const float2*)&Wih1[(size_t)(g * HSZ + h0 + u) * ESZ + k];
        int c = k >> 4, kk = k & 15;
        int tn = nl >> 3, rr = nl & 7, qq = (kk & 7) >> 1, f = (kk >= 8) ? 1 : 0;
        g_wf1[((size_t)(bn * 8 + tn) * 32 + c) * 64 + (rr * 4 + qq) * 2 + f] = pack2(v.x, v.y);
    }
}

// grid (64, 8): blockIdx.y splits the 32768 items
__global__ void pack_wf2(const float* __restrict__ Wih2)
{
    int bn = blockIdx.x, h0 = bn * 16;
    int base = blockIdx.y * 4096;
    for (int idx = base + threadIdx.x; idx < base + 4096; idx += 256) {
        int nl = idx >> 9, k = (idx & 511) * 2;
        int g = nl >> 4, u = nl & 15;
        float2 v = *(const float2*)&Wih2[(size_t)(g * HSZ + h0 + u) * HSZ + k];
        int c = k >> 4, kk = k & 15;
        int tn = nl >> 3, rr = nl & 7, qq = (kk & 7) >> 1, f = (kk >= 8) ? 1 : 0;
        g_wf2[((size_t)(bn * 8 + tn) * 64 + c) * 64 + (rr * 4 + qq) * 2 + f] = pack2(v.x, v.y);
    }
}

// lin_W (5000 x 1024) -> fp16 B-frags; grid (79, 8)
__global__ void pack_lwf(const float* __restrict__ linW)
{
    int nb = blockIdx.x, n0 = nb * 64;
    int base = blockIdx.y * 4096;
    for (int idx = base + threadIdx.x; idx < base + 4096; idx += 256) {
        int nl = idx >> 9, k = (idx & 511) * 2;
        int n = n0 + nl;
        float2 v = make_float2(0.f, 0.f);
        if (n < VSZ) v = *(const float2*)&linW[(size_t)n * HSZ + k];
        int c = k >> 4, kk = k & 15;
        int tn = nl >> 3, rr = nl & 7, qq = (kk & 7) >> 1, f = (kk >= 8) ? 1 : 0;
        g_lwf[((size_t)(nb * 8 + tn) * 64 + c) * 64 + (rr * 4 + qq) * 2 + f] = pack2(v.x, v.y);
    }
}

// ---------------- unified persistent kernel ---------------------------------
// 148 blocks x 512 threads:
//   blocks 0..63   : layer-1 recurrence (then join projection queue)
//   blocks 64..127 : layer-2 recurrence (then join projection queue)
//   blocks 128..147: projection workers from t=0 (queue gated on l2c[t0+1])
__global__ void __launch_bounds__(512, 1)
lstm_dual(const float* __restrict__ Whh1,
          const float* __restrict__ bi1,  const float* __restrict__ bh1,
          const float* __restrict__ Whh2,
          const float* __restrict__ bi2,  const float* __restrict__ bh2,
          const float* __restrict__ lin_b, float* __restrict__ out)
{
    extern __shared__ unsigned smu[];
    float* Gb = (float*)(smu + 32768);    // [4 grp][64][68]
    const int tid = threadIdx.x, lane = tid & 31, wid = tid >> 5;
    const int r = lane >> 2, q = lane & 3;
    unsigned* l1c = g_ctr;
    unsigned* l2c = g_ctr + TSZ;
    const bool isWorker = (blockIdx.x >= 128);

    if (!isWorker) {
        const int mt = wid & 3;
        const int kh = (wid >> 2) & 1;
        const int role = wid >> 3;
        const int grp = role * 2 + kh;
        const bool isL2 = (blockIdx.x >= 64);
        const int bn = isL2 ? (blockIdx.x - 64) : blockIdx.x;
        const int h0 = bn * 16;

        // ---- load W_hh slice into SMEM fp16 B-frags (once) ----
        {
            const float* Whh = isL2 ? Whh2 : Whh1;
            for (int idx = tid; idx < 64 * 512; idx += 512) {
                int nl = idx >> 9, k = (idx & 511) * 2;
                int g = nl >> 4, u = nl & 15;
                float2 v = *(const float2*)&Whh[(size_t)(g * HSZ + h0 + u) * HSZ + k];
                int c = k >> 4, kk = k & 15;
                int tn = nl >> 3, rr = nl & 7, qq = (kk & 7) >> 1, f = (kk >= 8) ? 1 : 0;
                smu[((tn * 64 + c) * 32 + rr * 4 + qq) * 2 + f] = pack2(v.x, v.y);
            }
        }
        __syncthreads();

        // epilogue mapping: thread -> col jb, rows rg*2, rg*2+1
        const int jb = tid & 15, rg = tid >> 4;
        float bia[4];
        {
            const float* bA = isL2 ? bi2 : bi1;
            const float* bB = isL2 ? bh2 : bh1;
            #pragma unroll
            for (int g = 0; g < 4; g++)
                bia[g] = bA[g * HSZ + h0 + jb] + bB[g * HSZ + h0 + jb];
        }
        int pk[2];
        #pragma unroll
        for (int i = 0; i < 2; i++) {
            int ri = rg * 2 + i, mti = ri >> 4, ml = ri & 15;
            int lp = (ml & 7) * 4 + ((jb & 7) >> 1);
            int e  = ((ml >= 8) ? 1 : 0) + ((jb >= 8) ? 2 : 0);
            pk[i]  = (((mti * 64 + bn) * 32 + lp) * 4 + e) * 2 + (jb & 1);
        }
        float cst[2] = {0.f, 0.f};

        for (int t = 0; t < TSZ; t++) {
            float acc[8][4];
            #pragma unroll
            for (int i = 0; i < 8; i++)
                #pragma unroll
                for (int j = 0; j < 4; j++) acc[i][j] = 0.f;

            if (!isL2) {
                if (role == 0) {
                    // x-part: K=512, W from L2, no dependency
                    const uint4* ax = (const uint4*)g_xf
                                      + ((size_t)(t * 4 + mt) * 32 + kh * 16) * 32 + lane;
                    const unsigned* wg = g_wf1 + ((size_t)(bn * 8) * 32 + kh * 16) * 64 + lane * 2;
                    #pragma unroll 8
                    for (int c = 0; c < 16; c++) {
                        uint4 a4 = __ldcg(ax + c * 32);
                        unsigned af[4] = { a4.x, a4.y, a4.z, a4.w };
                        #pragma unroll
                        for (int tn = 0; tn < 8; tn++) {
                            const uint2 b2 = __ldg((const uint2*)(wg + ((size_t)tn * 32 + c) * 64));
                            unsigned bg[2] = { b2.x, b2.y };
                            mma16(acc[tn], af, bg);
                        }
                    }
                } else if (t > 0) {
                    if (tid == 256) { while (ld_acquire(&l1c[t - 1]) < 64) { } }
                    BARG2();
                    const uint4* ah = (const uint4*)g_h1f + (size_t)(t - 1) * (FRAGBUF / 4)
                                      + (mt * 64 + kh * 32) * 32 + lane;
                    #pragma unroll 8
                    for (int c = 0; c < 32; c++) {
                        uint4 a4 = __ldcg(ah + c * 32);
                        unsigned af[4] = { a4.x, a4.y, a4.z, a4.w };
                        #pragma unroll
                        for (int tn = 0; tn < 8; tn++) {
                            const unsigned* p = smu + (tn * 64 + kh * 32 + c) * 64 + lane * 2;
                            unsigned bg[2] = { p[0], p[1] };
                            mma16(acc[tn], af, bg);
                        }
                    }
                }
            } else {
                if (role == 0) {
                    if (t > 0) {
                        if (tid == 0) { while (ld_acquire(&l2c[t - 1]) < 64) { } }
                        BARG1();
                        const uint4* ah = (const uint4*)g_h2f + (size_t)(t - 1) * (FRAGBUF / 4)
                                          + (mt * 64 + kh * 32) * 32 + lane;
                        #pragma unroll 8
                        for (int c = 0; c < 32; c++) {
                            uint4 a4 = __ldcg(ah + c * 32);
                            unsigned af[4] = { a4.x, a4.y, a4.z, a4.w };
                            #pragma unroll
                            for (int tn = 0; tn < 8; tn++) {
                                const unsigned* p = smu + (tn * 64 + kh * 32 + c) * 64 + lane * 2;
                                unsigned bg[2] = { p[0], p[1] };
                                mma16(acc[tn], af, bg);
                            }
                        }
                    }
                } else {
                    if (tid == 256) { while (ld_acquire(&l1c[t]) < 64) { } }
                    BARG2();
                    const uint4* ah1 = (const uint4*)g_h1f + (size_t)t * (FRAGBUF / 4)
                                       + (mt * 64 + kh * 32) * 32 + lane;
                    const unsigned* wg = g_wf2 + ((size_t)(bn * 8) * 64 + kh * 32) * 64 + lane * 2;
                    #pragma unroll 8
                    for (int c = 0; c < 32; c++) {
                        uint4 a4 = __ldcg(ah1 + c * 32);
                        unsigned af[4] = { a4.x, a4.y, a4.z, a4.w };
                        #pragma unroll
                        for (int tn = 0; tn < 8; tn++) {
                            const uint2 b2 = __ldg((const uint2*)(wg + ((size_t)tn * 64 + c) * 64));
                            unsigned bg[2] = { b2.x, b2.y };
                            mma16(acc[tn], af, bg);
                        }
                    }
                }
            }

            // ---- stage partial sums (per group) ----
            {
                float* gb = &Gb[grp * 64 * 68];
                #pragma unroll
                for (int tn = 0; tn < 8; tn++) {
                    int col = tn * 8 + 2 * q;
                    gb[(mt * 16 + r    ) * 68 + col]     = acc[tn][0];
                    gb[(mt * 16 + r    ) * 68 + col + 1] = acc[tn][1];
                    gb[(mt * 16 + r + 8) * 68 + col]     = acc[tn][2];
                    gb[(mt * 16 + r + 8) * 68 + col + 1] = acc[tn][3];
                }
            }
            __syncthreads();

            // ---- cell update: 2 rows per thread; MUFU.TANH activations ----
            __half* hfo = (__half*)((isL2 ? g_h2f : g_h1f) + (size_t)t * FRAGBUF);
            #pragma unroll
            for (int i = 0; i < 2; i++) {
                int ri = rg * 2 + i;
                float iv = bia[0], fv = bia[1], gv = bia[2], ov = bia[3];
                #pragma unroll
                for (int g = 0; g < 4; g++) {
                    const float* gb = &Gb[g * 64 * 68 + ri * 68];
                    iv += gb[jb]; fv += gb[16 + jb]; gv += gb[32 + jb]; ov += gb[48 + jb];
                }
                float si = sigm(iv), sf = sigm(fv), so = sigm(ov);
                float cn = sf * cst[i] + si * tanha(gv);
                float hn = so * tanha(cn);
                cst[i] = cn;
                hfo[pk[i]] = __float2half_rn(hn);
            }
            __syncthreads();           // h-frag STGs ordered before release (cumulativity)
            if (tid == 0) red_release(isL2 ? &l2c[t] : &l1c[t]);
        }
        __syncthreads();               // recurrence done; smu[0] now reusable
    }

    // ---------------- projection work queue -------------------------------
    // item = tp * NTILE + nb covers timesteps {2tp, 2tp+1}; gated on l2c[2tp+1].
    // 16 warps = 4 m-tiles x 4 n-quarters. A loads via __ldg: addresses are
    // first-touch per SM (full-history ring) -> safe, and L1 absorbs the 4x
    // nq duplication instead of hammering L2.
    {
        const int mt2 = wid & 3, nq = wid >> 2;
        for (;;) {
            if (tid == 0) smu[0] = atomicAdd(&g_q, 1u);
            __syncthreads();
            unsigned idx = smu[0];
            if (idx >= NITEMS2) break;
            int tp = idx / NTILE, nb2 = idx - tp * NTILE;
            int t0 = tp * 2;
            if (tid == 0) { while (ld_acquire(&l2c[t0 + 1]) < 64) { } }
            __syncthreads();           // acquire + protects smu[0] reuse

            float pa[2][2][4];
            #pragma unroll
            for (int s = 0; s < 2; s++)
                #pragma unroll
                for (int i = 0; i < 2; i++)
                    #pragma unroll
                    for (int j = 0; j < 4; j++) pa[s][i][j] = 0.f;

            const uint4* ab0 = (const uint4*)g_h2f + (size_t)t0 * (FRAGBUF / 4)
                               + (mt2 * 64) * 32 + lane;
            const uint4* ab1 = ab0 + (FRAGBUF / 4);
            const unsigned* wg = g_lwf + ((size_t)(nb2 * 8 + nq * 2) * 64) * 64 + lane * 2;

            #pragma unroll 4
            for (int c = 0; c < 64; c++) {
                uint4 a0 = __ldg(ab0 + c * 32);
                uint4 a1 = __ldg(ab1 + c * 32);
                unsigned af0[4] = { a0.x, a0.y, a0.z, a0.w };
                unsigned af1[4] = { a1.x, a1.y, a1.z, a1.w };
                #pragma unroll
                for (int tn = 0; tn < 2; tn++) {
                    const uint2 b2 = __ldg((const uint2*)(wg + ((size_t)tn * 64 + c) * 64));
                    unsigned bg[2] = { b2.x, b2.y };
                    mma16(pa[0][tn], af0, bg);
                    mma16(pa[1][tn], af1, bg);
                }
            }

            #pragma unroll
            for (int s = 0; s < 2; s++) {
                int t = t0 + s;
                #pragma unroll
                for (int tn = 0; tn < 2; tn++) {
                    int n = nb2 * 64 + (nq * 2 + tn) * 8 + 2 * q;
                    int b0r = mt2 * 16 + r;
                    if (n + 1 < VSZ) {
                        float bb0 = lin_b[n], bb1 = lin_b[n + 1];
                        float2 v0 = make_float2(pa[s][tn][0] + bb0, pa[s][tn][1] + bb1);
                        float2 v1 = make_float2(pa[s][tn][2] + bb0, pa[s][tn][3] + bb1);
                        *(float2*)&out[((size_t)b0r * TSZ + t) * VSZ + n]       = v0;
                        *(float2*)&out[((size_t)(b0r + 8) * TSZ + t) * VSZ + n] = v1;
                    } else if (n < VSZ) {
                        float bb0 = lin_b[n];
                        out[((size_t)b0r * TSZ + t) * VSZ + n]       = pa[s][tn][0] + bb0;
                        out[((size_t)(b0r + 8) * TSZ + t) * VSZ + n] = pa[s][tn][2] + bb0;
                    }
                }
            }
        }
    }
}

// ---------------- launch ----------------------------------------------------
#define SMEM_DUAL (32768 * 4 + 4 * 64 * 68 * 4)   // 200704 bytes

extern "C" void kernel_launch(void* const* d_in, const int* in_sizes, int n_in,
                              void* d_out, int out_size)
{
    const int*   input  = (const int*)  d_in[0];
    const float* embedW = (const float*)d_in[2];
    const float* W_ih1  = (const float*)d_in[3];
    const float* W_hh1  = (const float*)d_in[4];
    const float* b_ih1  = (const float*)d_in[5];
    const float* b_hh1  = (const float*)d_in[6];
    const float* W_ih2  = (const float*)d_in[7];
    const float* W_hh2  = (const float*)d_in[8];
    const float* b_ih2  = (const float*)d_in[9];
    const float* b_hh2  = (const float*)d_in[10];
    const float* lin_W  = (const float*)d_in[11];
    const float* lin_b  = (const float*)d_in[12];
    float* out = (float*)d_out;

    cudaFuncSetAttribute(lstm_dual,
                         cudaFuncAttributeMaxDynamicSharedMemorySize, SMEM_DUAL);

    zero_ctr_kernel<<<1, 2 * TSZ>>>();
    embed_frag<<<MROWS, 128>>>(input, embedW);
    pack_wf1<<<dim3(64, 4), 256>>>(W_ih1);
    pack_wf2<<<dim3(64, 8), 256>>>(W_ih2);
    pack_lwf<<<dim3(NTILE, 8), 256>>>(lin_W);

    lstm_dual<<<148, 512, SMEM_DUAL>>>(W_hh1, b_ih1, b_hh1,
                                       W_hh2, b_ih2, b_hh2,
                                       lin_b, out);
}